// round 16
// baseline (speedup 1.0000x reference)
#include <cuda_runtime.h>
#include <cuda_fp16.h>
#include <mma.h>

using namespace nvcuda;

#define N_NODES 100000
#define F 64
#define N_EDGES 500000
#define NCH 9
#define NEG 0.2f
#define TILE 128
#define NT ((N_NODES + TILE - 1) / TILE)   // 782
#define M_GROUPS (NCH * N_NODES)           // 900000
#define M_EDGES  (NCH * N_EDGES)           // 4500000
#define NB_SCAN  ((M_GROUPS + 1023) / 1024) // 879

#define XLDH 72
#define WLDH 72
#define PLD 20
#define XS_HALFS (128 * XLDH)
#define WS_HALFS (64 * WLDH)
#define PATCH_FLOATS (8 * 16 * PLD)
#define SMEM_L0 (XS_HALFS * 2 + WS_HALFS * 2 + PATCH_FLOATS * 4 + 2 * NCH * F * 4)
#define SMEM_L1 (XS_HALFS * 2 + WS_HALFS * 2 + PATCH_FLOATS * 4 + 2 * F * 4)

typedef unsigned long long ull;
typedef unsigned int uint;

typedef wmma::fragment<wmma::matrix_a, 16, 16, 16, __half, wmma::row_major> AFragH;
typedef wmma::fragment<wmma::matrix_b, 16, 16, 16, __half, wmma::row_major> BFragH;
typedef wmma::fragment<wmma::accumulator, 16, 16, 16, float> CFragH;

// ---------------- scratch (device globals; no allocations allowed) ----------
__device__ __half g_hh1[(size_t)NCH * N_NODES * F];
__device__ __half g_hh2[(size_t)NCH * N_NODES * F];
__device__ __half g_x1h[(size_t)NCH * N_NODES * F];
__device__ __half g_x2h[(size_t)NCH * N_NODES * F];
__device__ float g_ss1[M_GROUPS];
__device__ float g_sd1[M_GROUPS];
__device__ float g_ws1[M_GROUPS];
__device__ float g_ss2[M_GROUPS];
__device__ float g_sd2[M_GROUPS];
__device__ float g_ws2[M_GROUPS];
__device__ int   g_cnt[2 * M_GROUPS];               // per-layer CSR state
__device__ int   g_off[2 * M_GROUPS];
__device__ int   g_cur[2 * M_GROUPS];
__device__ int   g_bsum[2][1024];
__device__ int   g_boff[2][1024];
__device__ ull   g_edge[2 * (size_t)M_EDGES];       // packed (w<<32 | src)

// ---------------- side stream + events (static init; created once) ---------
static cudaStream_t s_side;
static cudaEvent_t  s_ea, s_eb0, s_eb1;
namespace {
struct SideInit {
    SideInit() {
        cudaStreamCreateWithFlags(&s_side, cudaStreamNonBlocking);
        cudaEventCreateWithFlags(&s_ea,  cudaEventDisableTiming);
        cudaEventCreateWithFlags(&s_eb0, cudaEventDisableTiming);
        cudaEventCreateWithFlags(&s_eb1, cudaEventDisableTiming);
    }
};
SideInit s_side_init;
}

// ---------------- helpers ----------------
__device__ __forceinline__ uint4 pack8h(const float* v) {
    __half2 h0 = __floats2half2_rn(v[0], v[1]);
    __half2 h1 = __floats2half2_rn(v[2], v[3]);
    __half2 h2 = __floats2half2_rn(v[4], v[5]);
    __half2 h3 = __floats2half2_rn(v[6], v[7]);
    uint4 u;
    u.x = *(uint*)&h0; u.y = *(uint*)&h1; u.z = *(uint*)&h2; u.w = *(uint*)&h3;
    return u;
}
__device__ __forceinline__ void unpack8h(uint4 u, float* v) {
    __half2 h0, h1, h2, h3;
    *(uint*)&h0 = u.x; *(uint*)&h1 = u.y; *(uint*)&h2 = u.z; *(uint*)&h3 = u.w;
    float2 f0 = __half22float2(h0), f1 = __half22float2(h1);
    float2 f2 = __half22float2(h2), f3 = __half22float2(h3);
    v[0] = f0.x; v[1] = f0.y; v[2] = f1.x; v[3] = f1.y;
    v[4] = f2.x; v[5] = f2.y; v[6] = f3.x; v[7] = f3.y;
}
__device__ __forceinline__ uint2 f4toh4(float4 v) {
    __half2 h0 = __floats2half2_rn(v.x, v.y);
    __half2 h1 = __floats2half2_rn(v.z, v.w);
    uint2 u;
    u.x = *(uint*)&h0; u.y = *(uint*)&h1;
    return u;
}

// ---------------- GEMM core (one channel) ----------------
__device__ __forceinline__ void gemm_channel(
    const AFragH* af, const __half* __restrict__ Wsm, float* __restrict__ patch,
    const float* __restrict__ ashc, const float* __restrict__ adshc,
    __half* __restrict__ hout, float* __restrict__ ssout,
    float* __restrict__ sdout, float* __restrict__ wsout,
    int rowbase, int tid)
{
    const int w = tid >> 5;
    const int lane = tid & 31;

    CFragH cf[4];
    #pragma unroll
    for (int f = 0; f < 4; f++) wmma::fill_fragment(cf[f], 0.f);

    #pragma unroll
    for (int kk = 0; kk < 4; kk++) {
        #pragma unroll
        for (int f = 0; f < 4; f++) {
            BFragH bf;
            wmma::load_matrix_sync(bf, &Wsm[(16 * kk) * WLDH + 16 * f], WLDH);
            wmma::mma_sync(cf[f], af[kk], bf, cf[f]);
        }
    }

    float* mypatch = patch + w * (16 * PLD);
    const int r = lane >> 1;
    const int half_ = lane & 1;
    const int grow = rowbase + 16 * w + r;
    float ps = 0.f, pd = 0.f;

    #pragma unroll
    for (int f = 0; f < 4; f++) {
        wmma::store_matrix_sync(mypatch, cf[f], PLD, wmma::mem_row_major);
        __syncwarp();
        const float* prow = &mypatch[r * PLD + 8 * half_];
        float v[8];
        #pragma unroll
        for (int j = 0; j < 8; j++) v[j] = prow[j];
        int cb = 16 * f + 8 * half_;
        float4 a0 = *(const float4*)&ashc[cb];
        float4 a1 = *(const float4*)&ashc[cb + 4];
        float4 d0 = *(const float4*)&adshc[cb];
        float4 d1 = *(const float4*)&adshc[cb + 4];
        ps += v[0]*a0.x + v[1]*a0.y + v[2]*a0.z + v[3]*a0.w
            + v[4]*a1.x + v[5]*a1.y + v[6]*a1.z + v[7]*a1.w;
        pd += v[0]*d0.x + v[1]*d0.y + v[2]*d0.z + v[3]*d0.w
            + v[4]*d1.x + v[5]*d1.y + v[6]*d1.z + v[7]*d1.w;
        if (grow < N_NODES)
            *(uint4*)&hout[(size_t)grow * F + cb] = pack8h(v);
        __syncwarp();
    }
    ps += __shfl_xor_sync(0xffffffffu, ps, 1);
    pd += __shfl_xor_sync(0xffffffffu, pd, 1);
    if (half_ == 0 && grow < N_NODES) {
        float e = ps + pd; e = e > 0.f ? e : NEG * e;
        ssout[grow] = ps; sdout[grow] = pd; wsout[grow] = __expf(e);
    }
}

// ---------------- layer-0 GEMM ----------------
__global__ __launch_bounds__(256, 2) void gat_gemm_l0(
    const float* __restrict__ Xg,
    const float* __restrict__ Wall,
    const float* __restrict__ asall,
    const float* __restrict__ adall)
{
    extern __shared__ char smraw[];
    __half* Xs  = (__half*)smraw;
    __half* Wsm = Xs + XS_HALFS;
    float* patch = (float*)(Wsm + WS_HALFS);
    float* vas = patch + PATCH_FLOATS;
    float* vad = vas + NCH * F;

    const int tile = blockIdx.x;
    const int tid = threadIdx.x;
    const int rowbase = tile * TILE;

    for (int i = tid; i < 128 * 16; i += 256) {
        int row = i >> 4, kg = i & 15;
        int gr = rowbase + row;
        float4 v = make_float4(0.f, 0.f, 0.f, 0.f);
        if (gr < N_NODES) v = *(const float4*)&Xg[(size_t)gr * F + 4 * kg];
        *(uint2*)&Xs[row * XLDH + 4 * kg] = f4toh4(v);
    }
    for (int i = tid; i < NCH * F / 4; i += 256) {
        *(float4*)&vas[4 * i] = *(const float4*)&asall[4 * i];
        *(float4*)&vad[4 * i] = *(const float4*)&adall[4 * i];
    }
    __syncthreads();

    const int w = tid >> 5;
    AFragH af[4];
    #pragma unroll
    for (int kk = 0; kk < 4; kk++)
        wmma::load_matrix_sync(af[kk], &Xs[(16 * w) * XLDH + 16 * kk], XLDH);

    for (int c = 0; c < NCH; c++) {
        __syncthreads();
        const float* W = Wall + (size_t)c * F * F;
        for (int i = tid; i < 64 * 16; i += 256) {
            int row = i >> 4, kg = i & 15;
            *(uint2*)&Wsm[row * WLDH + 4 * kg] = f4toh4(*(const float4*)&W[row * 64 + 4 * kg]);
        }
        __syncthreads();
        gemm_channel(af, Wsm, patch,
                     vas + c * F, vad + c * F,
                     g_hh1 + (size_t)c * N_NODES * F,
                     g_ss1 + (size_t)c * N_NODES,
                     g_sd1 + (size_t)c * N_NODES,
                     g_ws1 + (size_t)c * N_NODES,
                     rowbase, tid);
    }
}

// ---------------- layer-1 GEMM ----------------
__global__ __launch_bounds__(256, 2) void gat_gemm_l1(
    const float* __restrict__ Wall,
    const float* __restrict__ asall,
    const float* __restrict__ adall)
{
    extern __shared__ char smraw[];
    __half* Xs  = (__half*)smraw;
    __half* Wsm = Xs + XS_HALFS;
    float* patch = (float*)(Wsm + WS_HALFS);
    float* vas = patch + PATCH_FLOATS;
    float* vad = vas + F;

    const int bx = blockIdx.x;
    const int c = bx / NT;
    const int tile = bx % NT;
    const int tid = threadIdx.x;
    const int rowbase = tile * TILE;

    const __half* xin = g_x1h + (size_t)c * N_NODES * F;
    for (int i = tid; i < 128 * 8; i += 256) {
        int row = i >> 3, jg = i & 7;
        int gr = rowbase + row;
        uint4 hv = make_uint4(0u, 0u, 0u, 0u);
        if (gr < N_NODES) hv = *(const uint4*)&xin[(size_t)gr * F + 8 * jg];
        *(uint4*)&Xs[row * XLDH + 8 * jg] = hv;
    }
    const float* W = Wall + (size_t)c * F * F;
    for (int i = tid; i < 64 * 16; i += 256) {
        int row = i >> 4, kg = i & 15;
        *(uint2*)&Wsm[row * WLDH + 4 * kg] = f4toh4(*(const float4*)&W[row * 64 + 4 * kg]);
    }
    if (tid < F) {
        vas[tid] = asall[c * F + tid];
        vad[tid] = adall[c * F + tid];
    }
    __syncthreads();

    const int w = tid >> 5;
    AFragH af[4];
    #pragma unroll
    for (int kk = 0; kk < 4; kk++)
        wmma::load_matrix_sync(af[kk], &Xs[(16 * w) * XLDH + 16 * kk], XLDH);

    gemm_channel(af, Wsm, patch,
                 vas, vad,
                 g_hh2 + (size_t)c * N_NODES * F,
                 g_ss2 + (size_t)c * N_NODES,
                 g_sd2 + (size_t)c * N_NODES,
                 g_ws2 + (size_t)c * N_NODES,
                 rowbase, tid);
}

// ---------------- CSR build (per-layer arrays; runs on side stream) --------
__global__ __launch_bounds__(256) void k_zero(int layer)
{
    int i = blockIdx.x * 256 + threadIdx.x;
    if (i < M_GROUPS) g_cnt[layer * M_GROUPS + i] = 0;
}

__global__ __launch_bounds__(256) void k_count(const int* __restrict__ EI, int layer)
{
    int t = blockIdx.x * 256 + threadIdx.x;
    if (t >= M_EDGES) return;
    int c = t / N_EDGES;
    int e = t - c * N_EDGES;
    int d = EI[((size_t)(c * 2 + layer) * 2 + 1) * N_EDGES + e];
    atomicAdd(&g_cnt[layer * M_GROUPS + c * N_NODES + d], 1);
}

__global__ __launch_bounds__(256) void k_scan1(int layer)
{
    __shared__ int sh[256];
    const int* cnt = g_cnt + layer * M_GROUPS;
    int* off = g_off + layer * M_GROUPS;
    int tid = threadIdx.x;
    int base = blockIdx.x * 1024 + tid * 4;
    int v0 = 0, v1 = 0, v2 = 0, v3 = 0;
    if (base + 3 < M_GROUPS) {
        int4 t = *(const int4*)&cnt[base];
        v0 = t.x; v1 = t.y; v2 = t.z; v3 = t.w;
    } else {
        if (base     < M_GROUPS) v0 = cnt[base];
        if (base + 1 < M_GROUPS) v1 = cnt[base + 1];
        if (base + 2 < M_GROUPS) v2 = cnt[base + 2];
        if (base + 3 < M_GROUPS) v3 = cnt[base + 3];
    }
    int tsum = v0 + v1 + v2 + v3;
    sh[tid] = tsum;
    __syncthreads();
    for (int offs = 1; offs < 256; offs <<= 1) {
        int t = (tid >= offs) ? sh[tid - offs] : 0;
        __syncthreads();
        sh[tid] += t;
        __syncthreads();
    }
    int excl = sh[tid] - tsum;
    if (base     < M_GROUPS) off[base]     = excl;
    if (base + 1 < M_GROUPS) off[base + 1] = excl + v0;
    if (base + 2 < M_GROUPS) off[base + 2] = excl + v0 + v1;
    if (base + 3 < M_GROUPS) off[base + 3] = excl + v0 + v1 + v2;
    if (tid == 255) g_bsum[layer][blockIdx.x] = sh[255];
}

__global__ __launch_bounds__(1024) void k_scan2(int layer)
{
    __shared__ int sh[1024];
    int tid = threadIdx.x;
    int v = (tid < NB_SCAN) ? g_bsum[layer][tid] : 0;
    sh[tid] = v;
    __syncthreads();
    for (int offs = 1; offs < 1024; offs <<= 1) {
        int t = (tid >= offs) ? sh[tid - offs] : 0;
        __syncthreads();
        sh[tid] += t;
        __syncthreads();
    }
    if (tid < NB_SCAN) g_boff[layer][tid] = sh[tid] - v;
}

__global__ __launch_bounds__(256) void k_scan3(int layer)
{
    int i = blockIdx.x * 256 + threadIdx.x;
    if (i >= M_GROUPS) return;
    int base = layer * M_GROUPS;
    int v = g_off[base + i] + g_boff[layer][i >> 10];
    g_off[base + i] = v;
    g_cur[base + i] = v;
}

// scatter + per-edge weight; packed (w, src) single 8B store
__global__ __launch_bounds__(256) void k_scatter(const int* __restrict__ EI, int layer)
{
    int t = blockIdx.x * 256 + threadIdx.x;
    if (t >= M_EDGES) return;
    int c = t / N_EDGES;
    int e = t - c * N_EDGES;
    const int* src = EI + ((size_t)(c * 2 + layer) * 2) * N_EDGES;
    const int* dst = src + N_EDGES;
    int s = src[e];
    int d = dst[e];
    const float* ss = (layer ? g_ss2 : g_ss1) + (size_t)c * N_NODES;
    const float* sd = (layer ? g_sd2 : g_sd1) + (size_t)c * N_NODES;
    float ev = __ldg(&ss[s]) + __ldg(&sd[d]);
    ev = ev > 0.f ? ev : NEG * ev;
    float w = __expf(ev);
    int pos = atomicAdd(&g_cur[layer * M_GROUPS + c * N_NODES + d], 1);
    g_edge[(size_t)layer * M_EDGES + pos] = ((ull)__float_as_uint(w) << 32) | (uint)s;
}

// ---------------- gather aggregation (fp16 h) -> fp16 x --------------------
__global__ __launch_bounds__(256) void gat_aggregate(int layer, const float* __restrict__ b1all)
{
    int gid = blockIdx.x * 256 + threadIdx.x;
    int g = gid >> 3;
    int j = gid & 7;
    if (g >= M_GROUPS) return;
    int c = g / N_NODES;
    int node = g - c * N_NODES;

    const __half* h = (layer ? g_hh2 : g_hh1) + (size_t)c * N_NODES * F;
    float wself = (layer ? g_ws2 : g_ws1)[g];
    __half* xout = (layer ? g_x2h : g_x1h) + (size_t)c * N_NODES * F;
    const ull* edges = g_edge + (size_t)layer * M_EDGES;
    const int* off = g_off + layer * M_GROUPS;

    float v[8];
    unpack8h(*(const uint4*)(h + (size_t)node * F + 8 * j), v);
    float acc[8];
    #pragma unroll
    for (int t = 0; t < 8; t++) acc[t] = wself * v[t];
    float den = wself;

    int start = off[g];
    int end = (g == M_GROUPS - 1) ? M_EDGES : off[g + 1];
    for (int i = start; i < end; i++) {
        ull p = __ldg(&edges[i]);
        int s = (int)(uint)p;
        float w = __uint_as_float((uint)(p >> 32));
        unpack8h(__ldg((const uint4*)(h + (size_t)s * F + 8 * j)), v);
        #pragma unroll
        for (int t = 0; t < 8; t++) acc[t] += w * v[t];
        den += w;
    }
    float inv = 1.f / den;
    #pragma unroll
    for (int t = 0; t < 8; t++) acc[t] *= inv;
    if (layer == 0) {
        float4 b0 = __ldg((const float4*)&b1all[c * F + 8 * j]);
        float4 b1v = __ldg((const float4*)&b1all[c * F + 8 * j + 4]);
        acc[0] = fmaxf(acc[0] + b0.x, 0.f);
        acc[1] = fmaxf(acc[1] + b0.y, 0.f);
        acc[2] = fmaxf(acc[2] + b0.z, 0.f);
        acc[3] = fmaxf(acc[3] + b0.w, 0.f);
        acc[4] = fmaxf(acc[4] + b1v.x, 0.f);
        acc[5] = fmaxf(acc[5] + b1v.y, 0.f);
        acc[6] = fmaxf(acc[6] + b1v.z, 0.f);
        acc[7] = fmaxf(acc[7] + b1v.w, 0.f);
    }
    *(uint4*)&xout[(size_t)node * F + 8 * j] = pack8h(acc);
}

// ---------------- channel attention combine ----------------
__global__ __launch_bounds__(256) void gat_final(
    const float* __restrict__ b2, const float* __restrict__ att, float* __restrict__ out)
{
    __shared__ float attsh[NCH * F];
    __shared__ float b2sh[NCH * F];
    for (int i = threadIdx.x; i < NCH * F; i += 256) { attsh[i] = att[i]; b2sh[i] = b2[i]; }
    __syncthreads();

    int tid = blockIdx.x * 256 + threadIdx.x;
    int node = tid >> 4;
    int j = tid & 15;
    if (node >= N_NODES) return;

    float4 xs[NCH];
    float sc[NCH];
    #pragma unroll
    for (int c = 0; c < NCH; c++) {
        ull hb = __ldg((const ull*)(g_x2h + ((size_t)c * N_NODES + node) * F + 4 * j));
        __half2 p01, p23;
        *(uint*)&p01 = (uint)hb; *(uint*)&p23 = (uint)(hb >> 32);
        float2 f01 = __half22float2(p01), f23 = __half22float2(p23);
        int cb = c * F + 4 * j;
        float4 v = make_float4(f01.x + b2sh[cb + 0], f01.y + b2sh[cb + 1],
                               f23.x + b2sh[cb + 2], f23.y + b2sh[cb + 3]);
        xs[c] = v;
        sc[c] = v.x * attsh[cb + 0] + v.y * attsh[cb + 1] + v.z * attsh[cb + 2] + v.w * attsh[cb + 3];
    }
    #pragma unroll
    for (int off = 1; off < 16; off <<= 1) {
        #pragma unroll
        for (int c = 0; c < NCH; c++) sc[c] += __shfl_xor_sync(0xffffffffu, sc[c], off);
    }
    float mx = sc[0];
    #pragma unroll
    for (int c = 1; c < NCH; c++) mx = fmaxf(mx, sc[c]);
    float sum = 0.f;
    float wch[NCH];
    #pragma unroll
    for (int c = 0; c < NCH; c++) { wch[c] = __expf(sc[c] - mx); sum += wch[c]; }
    float inv = 1.f / sum;
    float4 o = make_float4(0.f, 0.f, 0.f, 0.f);
    #pragma unroll
    for (int c = 0; c < NCH; c++) {
        float a = wch[c] * inv;
        o.x += a * xs[c].x; o.y += a * xs[c].y; o.z += a * xs[c].z; o.w += a * xs[c].w;
    }
    *(float4*)&out[(size_t)node * F + 4 * j] = o;
}

// ---------------- launch ----------------
extern "C" void kernel_launch(void* const* d_in, const int* in_sizes, int n_in,
                              void* d_out, int out_size)
{
    const float* emb = (const float*)d_in[0];
    const float* W1  = (const float*)d_in[1];
    const float* as1 = (const float*)d_in[2];
    const float* ad1 = (const float*)d_in[3];
    const float* b1  = (const float*)d_in[4];
    const float* W2  = (const float*)d_in[5];
    const float* as2 = (const float*)d_in[6];
    const float* ad2 = (const float*)d_in[7];
    const float* b2  = (const float*)d_in[8];
    const float* att = (const float*)d_in[9];
    const int*   EI  = (const int*)d_in[10];
    float* out = (float*)d_out;

    cudaFuncSetAttribute(gat_gemm_l0, cudaFuncAttributeMaxDynamicSharedMemorySize, SMEM_L0);
    cudaFuncSetAttribute(gat_gemm_l1, cudaFuncAttributeMaxDynamicSharedMemorySize, SMEM_L1);

    const int grp_grid   = (M_GROUPS + 255) / 256;
    const int edge_grid  = (M_EDGES + 255) / 256;
    const int agg_grid   = (M_GROUPS * 8 + 255) / 256;
    const int fin_grid   = (N_NODES * 16 + 255) / 256;

    // ---- fork: CSR builds for BOTH layers on the side stream (depend only on EI)
    cudaEventRecord(s_ea, 0);
    cudaStreamWaitEvent(s_side, s_ea, 0);

    k_zero<<<grp_grid, 256, 0, s_side>>>(0);
    k_count<<<edge_grid, 256, 0, s_side>>>(EI, 0);
    k_scan1<<<NB_SCAN, 256, 0, s_side>>>(0);
    k_scan2<<<1, 1024, 0, s_side>>>(0);
    k_scan3<<<grp_grid, 256, 0, s_side>>>(0);
    cudaEventRecord(s_eb0, s_side);

    k_zero<<<grp_grid, 256, 0, s_side>>>(1);
    k_count<<<edge_grid, 256, 0, s_side>>>(EI, 1);
    k_scan1<<<NB_SCAN, 256, 0, s_side>>>(1);
    k_scan2<<<1, 1024, 0, s_side>>>(1);
    k_scan3<<<grp_grid, 256, 0, s_side>>>(1);
    cudaEventRecord(s_eb1, s_side);

    // ---- main stream: gemm_l0 runs concurrently with the CSR builds
    gat_gemm_l0<<<NT, 256, SMEM_L0>>>(emb, W1, as1, ad1);

    // ---- join layer-0 CSR, then the dependent chain
    cudaStreamWaitEvent(0, s_eb0, 0);
    k_scatter<<<edge_grid, 256>>>(EI, 0);
    gat_aggregate<<<agg_grid, 256>>>(0, b1);

    gat_gemm_l1<<<NCH * NT, 256, SMEM_L1>>>(W2, as2, ad2);

    cudaStreamWaitEvent(0, s_eb1, 0);
    k_scatter<<<edge_grid, 256>>>(EI, 1);
    gat_aggregate<<<agg_grid, 256>>>(1, b1);

    gat_final<<<fin_grid, 256>>>(b2, att, out);
}